// round 16
// baseline (speedup 1.0000x reference)
#include <cuda_runtime.h>
#include <cuda_bf16.h>
#include <cuda_fp16.h>
#include <cstdint>

// Problem constants
#define B_TOT   2048
#define SEQ     49
#define CDIM    512
#define NHEAD   16
#define HD      32
#define NWIN    64
#define MROWS   (B_TOT * SEQ)      // 100352
#define QKVCOLS 1536
#define SCALE   0.17677669529663687f  // 32^-0.5

// Scratch (no cudaMalloc). Device globals referenced ONLY in device code.
__device__ float g_q[(size_t)B_TOT * NHEAD * SEQ * HD];
__device__ float g_k[(size_t)B_TOT * NHEAD * SEQ * HD];
__device__ float g_v[(size_t)B_TOT * NHEAD * SEQ * HD];

// fp16 operands: A-side split hi/lo (error 2^-22), B-side single fp16.
__device__ __half gx_h[(size_t)MROWS * CDIM];
__device__ __half gx_l[(size_t)MROWS * CDIM];
__device__ __half g_oh[(size_t)MROWS * CDIM];
__device__ __half g_ol[(size_t)MROWS * CDIM];
__device__ __half w_qkv[(size_t)QKVCOLS * CDIM];
__device__ __half w_proj[(size_t)CDIM * CDIM];

// ---------------------------------------------------------------------------
// fp32 -> fp16 conversions. WHICH: 0 = x (hi/lo split), 1 = qkv_w, 2 = proj_w
// ---------------------------------------------------------------------------
template <int WHICH>
__global__ __launch_bounds__(256)
void convert_split(const float* __restrict__ src)
{
    const size_t i = (size_t)blockIdx.x * blockDim.x + threadIdx.x; // float4 idx
    float4 v = reinterpret_cast<const float4*>(src)[i];

    __half hx = __float2half(v.x);
    __half hy = __float2half(v.y);
    __half hz = __float2half(v.z);
    __half hw = __float2half(v.w);

    __half2 hp0 = __halves2half2(hx, hy);
    __half2 hp1 = __halves2half2(hz, hw);
    uint2 H;
    H.x = *reinterpret_cast<uint32_t*>(&hp0);
    H.y = *reinterpret_cast<uint32_t*>(&hp1);

    if (WHICH == 0) {
        __half lx = __float2half(v.x - __half2float(hx));
        __half ly = __float2half(v.y - __half2float(hy));
        __half lz = __float2half(v.z - __half2float(hz));
        __half lw = __float2half(v.w - __half2float(hw));
        __half2 lp0 = __halves2half2(lx, ly);
        __half2 lp1 = __halves2half2(lz, lw);
        uint2 L;
        L.x = *reinterpret_cast<uint32_t*>(&lp0);
        L.y = *reinterpret_cast<uint32_t*>(&lp1);
        reinterpret_cast<uint2*>(gx_h)[i] = H;
        reinterpret_cast<uint2*>(gx_l)[i] = L;
    } else if (WHICH == 1) {
        reinterpret_cast<uint2*>(w_qkv)[i] = H;
    } else {
        reinterpret_cast<uint2*>(w_proj)[i] = H;
    }
}

// ---------------------------------------------------------------------------
// MMA helpers
// ---------------------------------------------------------------------------
__device__ __forceinline__ void mma_fp16(float& c0, float& c1, float& c2, float& c3,
                                         uint32_t a0, uint32_t a1, uint32_t a2, uint32_t a3,
                                         uint32_t b0, uint32_t b1)
{
    asm volatile(
        "mma.sync.aligned.m16n8k16.row.col.f32.f16.f16.f32 "
        "{%0,%1,%2,%3},{%4,%5,%6,%7},{%8,%9},{%0,%1,%2,%3};"
        : "+f"(c0), "+f"(c1), "+f"(c2), "+f"(c3)
        : "r"(a0), "r"(a1), "r"(a2), "r"(a3), "r"(b0), "r"(b1));
}

__device__ __forceinline__ void ldsm4(uint32_t& r0, uint32_t& r1, uint32_t& r2, uint32_t& r3,
                                      uint32_t addr)
{
    asm volatile("ldmatrix.sync.aligned.m8n8.x4.shared.b16 {%0,%1,%2,%3},[%4];"
                 : "=r"(r0), "=r"(r1), "=r"(r2), "=r"(r3) : "r"(addr));
}

__device__ __forceinline__ void cp16(uint32_t dst, const void* src)
{
    asm volatile("cp.async.cg.shared.global [%0], [%1], 16;" :: "r"(dst), "l"(src));
}

// ---------------------------------------------------------------------------
// Tensor-core GEMM: 128x256 tile, 512 threads, fp16x2-asymmetric.
//   C[m][n] = sum_k A[m][k] * B[n][k],  A = Ah+Al (fp16 pair), B = fp16
// 3-stage cp.async ring. 2 MMAs per accumulator per k16 (was 3).
// ---------------------------------------------------------------------------
#define ROWB 80
#define TILE_A_BYTES (128 * ROWB)               // 10240
#define TILE_B_BYTES (256 * ROWB)               // 20480
#define STAGE_BYTES  (2 * TILE_A_BYTES + TILE_B_BYTES)   // 40960
#define NSTAGE 3
#define SMEM_DYN     (NSTAGE * STAGE_BYTES)              // 122880
#define OFF_AL TILE_A_BYTES
#define OFF_B  (2 * TILE_A_BYTES)

template <int MODE>
__global__ __launch_bounds__(512, 1)
void gemm_tc(const float* __restrict__ bias, float* __restrict__ Cout)
{
    extern __shared__ char smem[];
    const uint32_t smem_base = (uint32_t)__cvta_generic_to_shared(smem);

    const int tid  = threadIdx.x;
    const int bm   = blockIdx.y;
    const int bn   = blockIdx.x;
    const int lane = tid & 31;
    const int wid  = tid >> 5;
    const int warp_m = wid & 3;
    const int warp_n = wid >> 2;

    const __half* Ah = (MODE == 0) ? gx_h : g_oh;
    const __half* Al = (MODE == 0) ? gx_l : g_ol;
    const __half* Bs = (MODE == 0) ? w_qkv : w_proj;

    float acc[2][8][4];
#pragma unroll
    for (int mt = 0; mt < 2; mt++)
#pragma unroll
        for (int nt = 0; nt < 8; nt++)
#pragma unroll
            for (int r = 0; r < 4; r++) acc[mt][nt][r] = 0.0f;

    // Stage loader: A hi/lo 2x512 chunks + B 1024 chunks = 2048; 4 per thread.
    auto load_stage = [&](int stage, int k0) {
#pragma unroll
        for (int i = 0; i < 4; i++) {
            const int id = tid + i * 512;         // 0..2047
            const uint32_t sbase = smem_base + stage * STAGE_BYTES;
            if (id < 1024) {                      // A hi/lo
                const int half = id >> 9;
                const int c    = id & 511;
                const int row  = c >> 2;
                const int c16  = c & 3;
                const size_t off = (size_t)(bm * 128 + row) * CDIM + k0 + c16 * 8;
                const uint32_t d = sbase + half * OFF_AL + row * ROWB + c16 * 16;
                cp16(d, (half == 0 ? Ah : Al) + off);
            } else {                              // B single
                const int id2 = id - 1024;        // 0..1023
                const int row = id2 >> 2;         // 0..255
                const int c16 = id2 & 3;
                const size_t off = (size_t)(bn * 256 + row) * CDIM + k0 + c16 * 8;
                const uint32_t d = sbase + OFF_B + row * ROWB + c16 * 16;
                cp16(d, Bs + off);
            }
        }
    };

    auto compute_stage = [&](int stage) {
        const uint32_t sb = smem_base + stage * STAGE_BYTES;
#pragma unroll
        for (int ks = 0; ks < 32; ks += 16) {
            uint32_t ah[2][4], al[2][4];
#pragma unroll
            for (int mt = 0; mt < 2; mt++) {
                const uint32_t rowA = warp_m * 32 + mt * 16 + (lane & 15);
                const uint32_t addr = sb + rowA * ROWB + ks * 2 + (lane >> 4) * 16;
                ldsm4(ah[mt][0], ah[mt][1], ah[mt][2], ah[mt][3], addr);
                ldsm4(al[mt][0], al[mt][1], al[mt][2], al[mt][3], addr + OFF_AL);
            }
#pragma unroll
            for (int j = 0; j < 4; j++) {
                const uint32_t rowB = warp_n * 64 + (2 * j + (lane >> 4)) * 8 + (lane & 7);
                const uint32_t addr = sb + OFF_B + rowB * ROWB + ks * 2
                                      + ((lane >> 3) & 1) * 16;
                uint32_t b0, b1, b2, b3;
                ldsm4(b0, b1, b2, b3, addr);
#pragma unroll
                for (int mt = 0; mt < 2; mt++) {
                    float* c0 = acc[mt][2 * j];
                    mma_fp16(c0[0], c0[1], c0[2], c0[3],
                             ah[mt][0], ah[mt][1], ah[mt][2], ah[mt][3], b0, b1);
                    mma_fp16(c0[0], c0[1], c0[2], c0[3],
                             al[mt][0], al[mt][1], al[mt][2], al[mt][3], b0, b1);
                    float* c1 = acc[mt][2 * j + 1];
                    mma_fp16(c1[0], c1[1], c1[2], c1[3],
                             ah[mt][0], ah[mt][1], ah[mt][2], ah[mt][3], b2, b3);
                    mma_fp16(c1[0], c1[1], c1[2], c1[3],
                             al[mt][0], al[mt][1], al[mt][2], al[mt][3], b2, b3);
                }
            }
        }
    };

    const int KT = CDIM / 32;   // 16
    load_stage(0, 0);
    asm volatile("cp.async.commit_group;" ::: "memory");
    load_stage(1, 32);
    asm volatile("cp.async.commit_group;" ::: "memory");

    for (int kt = 0; kt < KT; kt++) {
        if (kt + 1 < KT) {
            asm volatile("cp.async.wait_group 1;" ::: "memory");
        } else {
            asm volatile("cp.async.wait_group 0;" ::: "memory");
        }
        __syncthreads();
        if (kt + 2 < KT) {
            load_stage((kt + 2) % NSTAGE, (kt + 2) * 32);
            asm volatile("cp.async.commit_group;" ::: "memory");
        }
        compute_stage(kt % NSTAGE);
    }

    const int g = lane >> 2;
    const int q = lane & 3;
#pragma unroll
    for (int mt = 0; mt < 2; mt++) {
        const int m0 = bm * 128 + warp_m * 32 + mt * 16 + g;
#pragma unroll
        for (int nt = 0; nt < 8; nt++) {
            const int col0 = bn * 256 + warp_n * 64 + nt * 8 + 2 * q;
#pragma unroll
            for (int half = 0; half < 2; half++) {
                const int m = m0 + half * 8;
                const int b_idx = m / SEQ;
                const int n_idx = m - b_idx * SEQ;
#pragma unroll
                for (int e = 0; e < 2; e++) {
                    const int col = col0 + e;
                    float val = acc[mt][nt][half * 2 + e] + bias[col];
                    if (MODE == 0) {
                        const int s = col >> 9;
                        const int h = (col >> 5) & 15;
                        const int d = col & 31;
                        const size_t off =
                            ((((size_t)b_idx * NHEAD + h) * SEQ) + n_idx) * HD + d;
                        if (s == 0)      g_q[off] = val * SCALE;
                        else if (s == 1) g_k[off] = val;
                        else             g_v[off] = val;
                    } else {
                        Cout[(size_t)m * CDIM + col] = val;
                    }
                }
            }
        }
    }
}

// ---------------------------------------------------------------------------
// Attention (R14/R15 validated): transposed qT/kT float4 QK; PV 4i x 4d;
// bias+mask in QK epilogue. Output split now fp16 hi/lo.
// ---------------------------------------------------------------------------
__global__ __launch_bounds__(256)
void attn_kernel(const float* __restrict__ mask,
                 const float* __restrict__ table,
                 const int* __restrict__ relidx)
{
    const int h = blockIdx.x;
    const int b = blockIdx.y;
    const int tid = threadIdx.x;

    __shared__ float qT[32][52];      // [d][i]
    __shared__ float kT[32][52];      // [d][j]
    __shared__ float vs[49][36];      // [j][d]
    __shared__ float S[52][52];

    const size_t base = (((size_t)b * NHEAD + h) * SEQ) * HD;

    for (int idx = tid; idx < SEQ * HD; idx += 256) {
        const int r = idx >> 5, c = idx & 31;
        qT[c][r] = g_q[base + idx];
        kT[c][r] = g_k[base + idx];
        vs[r][c] = g_v[base + idx];
    }
    __syncthreads();

    const float* mptr = mask + (size_t)(b & (NWIN - 1)) * SEQ * SEQ;

    if (tid < 169) {
        const int i0 = (tid / 13) * 4;
        const int j0 = (tid - (tid / 13) * 13) * 4;
        float acc[4][4];
#pragma unroll
        for (int a = 0; a < 4; a++)
#pragma unroll
            for (int c = 0; c < 4; c++) acc[a][c] = 0.0f;
#pragma unroll
        for (int d = 0; d < HD; d++) {
            const float4 qv = *reinterpret_cast<const float4*>(&qT[d][i0]);
            const float4 kv = *reinterpret_cast<const float4*>(&kT[d][j0]);
            const float qa[4] = {qv.x, qv.y, qv.z, qv.w};
            const float ka[4] = {kv.x, kv.y, kv.z, kv.w};
#pragma unroll
            for (int a = 0; a < 4; a++)
#pragma unroll
                for (int c = 0; c < 4; c++)
                    acc[a][c] = fmaf(qa[a], ka[c], acc[a][c]);
        }
#pragma unroll
        for (int a = 0; a < 4; a++) {
            const int i = i0 + a;
            if (i < SEQ) {
#pragma unroll
                for (int c = 0; c < 4; c++) {
                    const int j = j0 + c;
                    if (j < SEQ) {
                        const int idx = i * SEQ + j;
                        S[i][j] = acc[a][c] + table[relidx[idx] * NHEAD + h] + mptr[idx];
                    }
                }
            }
        }
    }
    __syncthreads();

    {
        const int w    = tid >> 5;
        const int lane = tid & 31;
        for (int r = w; r < SEQ; r += 8) {
            const float v0 = (lane < SEQ)      ? S[r][lane]      : -1e30f;
            const float v1 = (lane + 32 < SEQ) ? S[r][lane + 32] : -1e30f;
            float mx = fmaxf(v0, v1);
#pragma unroll
            for (int o = 16; o > 0; o >>= 1)
                mx = fmaxf(mx, __shfl_xor_sync(0xFFFFFFFFu, mx, o));
            const float e0 = (lane < SEQ)      ? __expf(v0 - mx) : 0.0f;
            const float e1 = (lane + 32 < SEQ) ? __expf(v1 - mx) : 0.0f;
            float sum = e0 + e1;
#pragma unroll
            for (int o = 16; o > 0; o >>= 1)
                sum += __shfl_xor_sync(0xFFFFFFFFu, sum, o);
            const float inv = 1.0f / sum;
            if (lane < SEQ)      S[r][lane]      = e0 * inv;
            if (lane + 32 < SEQ) S[r][lane + 32] = e1 * inv;
        }
    }
    __syncthreads();

    if (tid < 104) {
        const int i0 = (tid / 8) * 4;
        const int d0 = (tid - (tid / 8) * 8) * 4;
        float acc[4][4];
#pragma unroll
        for (int a = 0; a < 4; a++)
#pragma unroll
            for (int e = 0; e < 4; e++) acc[a][e] = 0.0f;
        for (int j = 0; j < SEQ; j++) {
            const float4 vv = *reinterpret_cast<const float4*>(&vs[j][d0]);
            const float va[4] = {vv.x, vv.y, vv.z, vv.w};
#pragma unroll
            for (int a = 0; a < 4; a++) {
                const float sv = S[i0 + a][j];
#pragma unroll
                for (int e = 0; e < 4; e++)
                    acc[a][e] = fmaf(sv, va[e], acc[a][e]);
            }
        }
#pragma unroll
        for (int a = 0; a < 4; a++) {
            const int i = i0 + a;
            if (i < SEQ) {
                const size_t oo = ((size_t)b * SEQ + i) * CDIM + h * HD + d0;
#pragma unroll
                for (int e = 0; e < 4; e++) {
                    const float o = acc[a][e];
                    __half hi = __float2half(o);
                    g_oh[oo + e] = hi;
                    g_ol[oo + e] = __float2half(o - __half2float(hi));
                }
            }
        }
    }
}

// ---------------------------------------------------------------------------
extern "C" void kernel_launch(void* const* d_in, const int* in_sizes, int n_in,
                              void* d_out, int out_size)
{
    const float* x      = nullptr;
    const float* mask   = nullptr;
    const float* qkv_w  = nullptr;
    const float* qkv_b  = nullptr;
    const float* proj_w = nullptr;
    const float* proj_b = nullptr;
    const float* table  = nullptr;
    const int*   relidx = nullptr;

    for (int i = 0; i < n_in; i++) {
        switch (in_sizes[i]) {
            case 51380224: x      = (const float*)d_in[i]; break;
            case 153664:   mask   = (const float*)d_in[i]; break;
            case 786432:   qkv_w  = (const float*)d_in[i]; break;
            case 1536:     qkv_b  = (const float*)d_in[i]; break;
            case 262144:   proj_w = (const float*)d_in[i]; break;
            case 512:      proj_b = (const float*)d_in[i]; break;
            case 2704:     table  = (const float*)d_in[i]; break;
            case 2401:     relidx = (const int*)  d_in[i]; break;
            default: break;
        }
    }
    float* out = (float*)d_out;

    cudaFuncSetAttribute(gemm_tc<0>, cudaFuncAttributeMaxDynamicSharedMemorySize, SMEM_DYN);
    cudaFuncSetAttribute(gemm_tc<1>, cudaFuncAttributeMaxDynamicSharedMemorySize, SMEM_DYN);

    convert_split<0><<<(MROWS * CDIM / 4) / 256, 256>>>(x);
    convert_split<1><<<(QKVCOLS * CDIM / 4) / 256, 256>>>(qkv_w);
    convert_split<2><<<(CDIM * CDIM / 4) / 256, 256>>>(proj_w);

    {
        dim3 grid(QKVCOLS / 256, MROWS / 128);   // (6, 784)
        gemm_tc<0><<<grid, 512, SMEM_DYN>>>(qkv_b, nullptr);
    }
    {
        dim3 grid(NHEAD, B_TOT);
        attn_kernel<<<grid, 256>>>(mask, table, relidx);
    }
    {
        dim3 grid(CDIM / 256, MROWS / 128);      // (2, 784)
        gemm_tc<1><<<grid, 512, SMEM_DYN>>>(proj_b, out);
    }
}

// round 17
// speedup vs baseline: 1.5175x; 1.5175x over previous
#include <cuda_runtime.h>
#include <cuda_bf16.h>
#include <cstdint>

// Problem constants
#define B_TOT   2048
#define SEQ     49
#define CDIM    512
#define NHEAD   16
#define HD      32
#define NWIN    64
#define MROWS   (B_TOT * SEQ)      // 100352
#define QKVCOLS 1536
#define SCALE   0.17677669529663687f  // 32^-0.5

// Scratch (no cudaMalloc). Device globals referenced ONLY in device code.
__device__ float g_q[(size_t)B_TOT * NHEAD * SEQ * HD];
__device__ float g_k[(size_t)B_TOT * NHEAD * SEQ * HD];
__device__ float g_v[(size_t)B_TOT * NHEAD * SEQ * HD];

// Pre-split bf16 operands (hi/lo) for the bf16x3 GEMMs
__device__ __nv_bfloat16 gx_h[(size_t)MROWS * CDIM];
__device__ __nv_bfloat16 gx_l[(size_t)MROWS * CDIM];
__device__ __nv_bfloat16 g_oh[(size_t)MROWS * CDIM];
__device__ __nv_bfloat16 g_ol[(size_t)MROWS * CDIM];
__device__ __nv_bfloat16 w_qkvh[(size_t)QKVCOLS * CDIM];
__device__ __nv_bfloat16 w_qkvl[(size_t)QKVCOLS * CDIM];
__device__ __nv_bfloat16 w_projh[(size_t)CDIM * CDIM];
__device__ __nv_bfloat16 w_projl[(size_t)CDIM * CDIM];

// ---------------------------------------------------------------------------
// fp32 -> (hi,lo) bf16 split conversion. WHICH: 0=x 1=qkv_w 2=proj_w
// ---------------------------------------------------------------------------
template <int WHICH>
__global__ __launch_bounds__(256)
void convert_split(const float* __restrict__ src)
{
    const size_t i = (size_t)blockIdx.x * blockDim.x + threadIdx.x; // float4 idx
    float4 v = reinterpret_cast<const float4*>(src)[i];

    __nv_bfloat16 hx = __float2bfloat16(v.x);
    __nv_bfloat16 hy = __float2bfloat16(v.y);
    __nv_bfloat16 hz = __float2bfloat16(v.z);
    __nv_bfloat16 hw = __float2bfloat16(v.w);
    __nv_bfloat16 lx = __float2bfloat16(v.x - __bfloat162float(hx));
    __nv_bfloat16 ly = __float2bfloat16(v.y - __bfloat162float(hy));
    __nv_bfloat16 lz = __float2bfloat16(v.z - __bfloat162float(hz));
    __nv_bfloat16 lw = __float2bfloat16(v.w - __bfloat162float(hw));

    __nv_bfloat162 hp0 = __halves2bfloat162(hx, hy);
    __nv_bfloat162 hp1 = __halves2bfloat162(hz, hw);
    __nv_bfloat162 lp0 = __halves2bfloat162(lx, ly);
    __nv_bfloat162 lp1 = __halves2bfloat162(lz, lw);

    uint2 H, L;
    H.x = *reinterpret_cast<uint32_t*>(&hp0);
    H.y = *reinterpret_cast<uint32_t*>(&hp1);
    L.x = *reinterpret_cast<uint32_t*>(&lp0);
    L.y = *reinterpret_cast<uint32_t*>(&lp1);

    __nv_bfloat16 *dh, *dl;
    if (WHICH == 0)      { dh = gx_h;   dl = gx_l;   }
    else if (WHICH == 1) { dh = w_qkvh; dl = w_qkvl; }
    else                 { dh = w_projh; dl = w_projl; }
    reinterpret_cast<uint2*>(dh)[i] = H;
    reinterpret_cast<uint2*>(dl)[i] = L;
}

// ---------------------------------------------------------------------------
// Shared MMA helpers
// ---------------------------------------------------------------------------
__device__ __forceinline__ void mma_bf16(float& c0, float& c1, float& c2, float& c3,
                                         uint32_t a0, uint32_t a1, uint32_t a2, uint32_t a3,
                                         uint32_t b0, uint32_t b1)
{
    asm volatile(
        "mma.sync.aligned.m16n8k16.row.col.f32.bf16.bf16.f32 "
        "{%0,%1,%2,%3},{%4,%5,%6,%7},{%8,%9},{%0,%1,%2,%3};"
        : "+f"(c0), "+f"(c1), "+f"(c2), "+f"(c3)
        : "r"(a0), "r"(a1), "r"(a2), "r"(a3), "r"(b0), "r"(b1));
}

__device__ __forceinline__ void ldsm4(uint32_t& r0, uint32_t& r1, uint32_t& r2, uint32_t& r3,
                                      uint32_t addr)
{
    asm volatile("ldmatrix.sync.aligned.m8n8.x4.shared.b16 {%0,%1,%2,%3},[%4];"
                 : "=r"(r0), "=r"(r1), "=r"(r2), "=r"(r3) : "r"(addr));
}

__device__ __forceinline__ void cp16(uint32_t dst, const void* src)
{
    asm volatile("cp.async.cg.shared.global [%0], [%1], 16;" :: "r"(dst), "l"(src));
}

// ---------------------------------------------------------------------------
// Tensor-core GEMM (R15 validated): 128x256 tile, 512 threads, bf16x3,
// 3-stage cp.async ring.
// ---------------------------------------------------------------------------
#define ROWB 80
#define TILE_A_BYTES (128 * ROWB)
#define TILE_B_BYTES (256 * ROWB)
#define STAGE_BYTES  (2 * TILE_A_BYTES + 2 * TILE_B_BYTES)   // 61440
#define NSTAGE 3
#define SMEM_DYN     (NSTAGE * STAGE_BYTES)                  // 184320
#define OFF_AL TILE_A_BYTES
#define OFF_BH (2 * TILE_A_BYTES)
#define OFF_BL (2 * TILE_A_BYTES + TILE_B_BYTES)

template <int MODE>
__global__ __launch_bounds__(512, 1)
void gemm_tc(const float* __restrict__ bias, float* __restrict__ Cout)
{
    extern __shared__ char smem[];
    const uint32_t smem_base = (uint32_t)__cvta_generic_to_shared(smem);

    const int tid  = threadIdx.x;
    const int bm   = blockIdx.y;
    const int bn   = blockIdx.x;
    const int lane = tid & 31;
    const int wid  = tid >> 5;
    const int warp_m = wid & 3;
    const int warp_n = wid >> 2;

    const __nv_bfloat16* Ah = (MODE == 0) ? gx_h : g_oh;
    const __nv_bfloat16* Al = (MODE == 0) ? gx_l : g_ol;
    const __nv_bfloat16* Bh = (MODE == 0) ? w_qkvh : w_projh;
    const __nv_bfloat16* Bl = (MODE == 0) ? w_qkvl : w_projl;

    float acc[2][8][4];
#pragma unroll
    for (int mt = 0; mt < 2; mt++)
#pragma unroll
        for (int nt = 0; nt < 8; nt++)
#pragma unroll
            for (int r = 0; r < 4; r++) acc[mt][nt][r] = 0.0f;

    auto load_stage = [&](int stage, int k0) {
#pragma unroll
        for (int i = 0; i < 6; i++) {
            const int id = tid + i * 512;
            const uint32_t sbase = smem_base + stage * STAGE_BYTES;
            if (id < 1024) {
                const int half = id >> 9;
                const int c    = id & 511;
                const int row  = c >> 2;
                const int c16  = c & 3;
                const size_t off = (size_t)(bm * 128 + row) * CDIM + k0 + c16 * 8;
                const uint32_t d = sbase + half * OFF_AL + row * ROWB + c16 * 16;
                cp16(d, (half == 0 ? Ah : Al) + off);
            } else {
                const int id2  = id - 1024;
                const int half = id2 >> 10;
                const int c    = id2 & 1023;
                const int row  = c >> 2;
                const int c16  = c & 3;
                const size_t off = (size_t)(bn * 256 + row) * CDIM + k0 + c16 * 8;
                const uint32_t d = sbase + OFF_BH + half * TILE_B_BYTES
                                   + row * ROWB + c16 * 16;
                cp16(d, (half == 0 ? Bh : Bl) + off);
            }
        }
    };

    auto compute_stage = [&](int stage) {
        const uint32_t sb = smem_base + stage * STAGE_BYTES;
#pragma unroll
        for (int ks = 0; ks < 32; ks += 16) {
            uint32_t ah[2][4], al[2][4];
#pragma unroll
            for (int mt = 0; mt < 2; mt++) {
                const uint32_t rowA = warp_m * 32 + mt * 16 + (lane & 15);
                const uint32_t addr = sb + rowA * ROWB + ks * 2 + (lane >> 4) * 16;
                ldsm4(ah[mt][0], ah[mt][1], ah[mt][2], ah[mt][3], addr);
                ldsm4(al[mt][0], al[mt][1], al[mt][2], al[mt][3], addr + OFF_AL);
            }
#pragma unroll
            for (int j = 0; j < 4; j++) {
                const uint32_t rowB = warp_n * 64 + (2 * j + (lane >> 4)) * 8 + (lane & 7);
                const uint32_t addr = sb + OFF_BH + rowB * ROWB + ks * 2
                                      + ((lane >> 3) & 1) * 16;
                uint32_t bh0, bh1, bh2, bh3, bl0, bl1, bl2, bl3;
                ldsm4(bh0, bh1, bh2, bh3, addr);
                ldsm4(bl0, bl1, bl2, bl3, addr + TILE_B_BYTES);
#pragma unroll
                for (int mt = 0; mt < 2; mt++) {
                    float* c0 = acc[mt][2 * j];
                    mma_bf16(c0[0], c0[1], c0[2], c0[3],
                             ah[mt][0], ah[mt][1], ah[mt][2], ah[mt][3], bh0, bh1);
                    mma_bf16(c0[0], c0[1], c0[2], c0[3],
                             ah[mt][0], ah[mt][1], ah[mt][2], ah[mt][3], bl0, bl1);
                    mma_bf16(c0[0], c0[1], c0[2], c0[3],
                             al[mt][0], al[mt][1], al[mt][2], al[mt][3], bh0, bh1);
                    float* c1 = acc[mt][2 * j + 1];
                    mma_bf16(c1[0], c1[1], c1[2], c1[3],
                             ah[mt][0], ah[mt][1], ah[mt][2], ah[mt][3], bh2, bh3);
                    mma_bf16(c1[0], c1[1], c1[2], c1[3],
                             ah[mt][0], ah[mt][1], ah[mt][2], ah[mt][3], bl2, bl3);
                    mma_bf16(c1[0], c1[1], c1[2], c1[3],
                             al[mt][0], al[mt][1], al[mt][2], al[mt][3], bh2, bh3);
                }
            }
        }
    };

    const int KT = CDIM / 32;   // 16
    load_stage(0, 0);
    asm volatile("cp.async.commit_group;" ::: "memory");
    load_stage(1, 32);
    asm volatile("cp.async.commit_group;" ::: "memory");

    for (int kt = 0; kt < KT; kt++) {
        if (kt + 1 < KT) {
            asm volatile("cp.async.wait_group 1;" ::: "memory");
        } else {
            asm volatile("cp.async.wait_group 0;" ::: "memory");
        }
        __syncthreads();
        if (kt + 2 < KT) {
            load_stage((kt + 2) % NSTAGE, (kt + 2) * 32);
            asm volatile("cp.async.commit_group;" ::: "memory");
        }
        compute_stage(kt % NSTAGE);
    }

    const int g = lane >> 2;
    const int q = lane & 3;
#pragma unroll
    for (int mt = 0; mt < 2; mt++) {
        const int m0 = bm * 128 + warp_m * 32 + mt * 16 + g;
#pragma unroll
        for (int nt = 0; nt < 8; nt++) {
            const int col0 = bn * 256 + warp_n * 64 + nt * 8 + 2 * q;
#pragma unroll
            for (int half = 0; half < 2; half++) {
                const int m = m0 + half * 8;
                const int b_idx = m / SEQ;
                const int n_idx = m - b_idx * SEQ;
#pragma unroll
                for (int e = 0; e < 2; e++) {
                    const int col = col0 + e;
                    float val = acc[mt][nt][half * 2 + e] + bias[col];
                    if (MODE == 0) {
                        const int s = col >> 9;
                        const int h = (col >> 5) & 15;
                        const int d = col & 31;
                        const size_t off =
                            ((((size_t)b_idx * NHEAD + h) * SEQ) + n_idx) * HD + d;
                        if (s == 0)      g_q[off] = val * SCALE;
                        else if (s == 1) g_k[off] = val;
                        else             g_v[off] = val;
                    } else {
                        Cout[(size_t)m * CDIM + col] = val;
                    }
                }
            }
        }
    }
}

// ---------------------------------------------------------------------------
// R17 attention: one block per (head, window), 256 threads.
// QK re-tiled 4i x 3j (221/256 threads), PV re-tiled 2i x 4d (200/256).
// Per-accumulator arithmetic order unchanged from R14/R15.
// ---------------------------------------------------------------------------
__global__ __launch_bounds__(256)
void attn_kernel(const float* __restrict__ mask,
                 const float* __restrict__ table,
                 const int* __restrict__ relidx)
{
    const int h = blockIdx.x;
    const int b = blockIdx.y;
    const int tid = threadIdx.x;

    __shared__ float qT[32][52];      // [d][i]
    __shared__ float kT[32][52];      // [d][j]
    __shared__ float vs[49][36];      // [j][d]
    __shared__ float S[52][52];

    const size_t base = (((size_t)b * NHEAD + h) * SEQ) * HD;

    for (int idx = tid; idx < SEQ * HD; idx += 256) {
        const int r = idx >> 5, c = idx & 31;
        qT[c][r] = g_q[base + idx];
        kT[c][r] = g_k[base + idx];
        vs[r][c] = g_v[base + idx];
    }
    __syncthreads();

    const float* mptr = mask + (size_t)(b & (NWIN - 1)) * SEQ * SEQ;

    // ---- QK: 13 i-tiles x 17 j-tiles of 4i x 3j (221 threads) ----
    if (tid < 221) {
        const int it = tid / 17;
        const int jt = tid - it * 17;
        const int i0 = it * 4;
        const int j0 = jt * 3;
        float acc[4][3];
#pragma unroll
        for (int a = 0; a < 4; a++)
#pragma unroll
            for (int c = 0; c < 3; c++) acc[a][c] = 0.0f;
#pragma unroll
        for (int d = 0; d < HD; d++) {
            const float4 qv = *reinterpret_cast<const float4*>(&qT[d][i0]);
            const float qa[4] = {qv.x, qv.y, qv.z, qv.w};
            float ka[3];
#pragma unroll
            for (int c = 0; c < 3; c++) ka[c] = kT[d][j0 + c];
#pragma unroll
            for (int a = 0; a < 4; a++)
#pragma unroll
                for (int c = 0; c < 3; c++)
                    acc[a][c] = fmaf(qa[a], ka[c], acc[a][c]);
        }
#pragma unroll
        for (int a = 0; a < 4; a++) {
            const int i = i0 + a;
            if (i < SEQ) {
#pragma unroll
                for (int c = 0; c < 3; c++) {
                    const int j = j0 + c;
                    if (j < SEQ) {
                        const int idx = i * SEQ + j;
                        S[i][j] = acc[a][c] + table[relidx[idx] * NHEAD + h] + mptr[idx];
                    }
                }
            }
        }
    }
    __syncthreads();

    // ---- warp-parallel softmax ----
    {
        const int w    = tid >> 5;
        const int lane = tid & 31;
        for (int r = w; r < SEQ; r += 8) {
            const float v0 = (lane < SEQ)      ? S[r][lane]      : -1e30f;
            const float v1 = (lane + 32 < SEQ) ? S[r][lane + 32] : -1e30f;
            float mx = fmaxf(v0, v1);
#pragma unroll
            for (int o = 16; o > 0; o >>= 1)
                mx = fmaxf(mx, __shfl_xor_sync(0xFFFFFFFFu, mx, o));
            const float e0 = (lane < SEQ)      ? __expf(v0 - mx) : 0.0f;
            const float e1 = (lane + 32 < SEQ) ? __expf(v1 - mx) : 0.0f;
            float sum = e0 + e1;
#pragma unroll
            for (int o = 16; o > 0; o >>= 1)
                sum += __shfl_xor_sync(0xFFFFFFFFu, sum, o);
            const float inv = 1.0f / sum;
            if (lane < SEQ)      S[r][lane]      = e0 * inv;
            if (lane + 32 < SEQ) S[r][lane + 32] = e1 * inv;
        }
    }
    __syncthreads();

    // ---- PV: 25 i-tiles x 8 d-tiles of 2i x 4d (200 threads) ----
    if (tid < 200) {
        const int it = tid / 8;
        const int dt = tid - it * 8;
        const int i0 = it * 2;
        const int d0 = dt * 4;
        float acc[2][4];
#pragma unroll
        for (int a = 0; a < 2; a++)
#pragma unroll
            for (int e = 0; e < 4; e++) acc[a][e] = 0.0f;
        for (int j = 0; j < SEQ; j++) {
            const float4 vv = *reinterpret_cast<const float4*>(&vs[j][d0]);
            const float va[4] = {vv.x, vv.y, vv.z, vv.w};
#pragma unroll
            for (int a = 0; a < 2; a++) {
                const float sv = S[i0 + a][j];
#pragma unroll
                for (int e = 0; e < 4; e++)
                    acc[a][e] = fmaf(sv, va[e], acc[a][e]);
            }
        }
#pragma unroll
        for (int a = 0; a < 2; a++) {
            const int i = i0 + a;
            if (i < SEQ) {
                const size_t oo = ((size_t)b * SEQ + i) * CDIM + h * HD + d0;
#pragma unroll
                for (int e = 0; e < 4; e++) {
                    const float o = acc[a][e];
                    __nv_bfloat16 hi = __float2bfloat16(o);
                    g_oh[oo + e] = hi;
                    g_ol[oo + e] = __float2bfloat16(o - __bfloat162float(hi));
                }
            }
        }
    }
}

// ---------------------------------------------------------------------------
extern "C" void kernel_launch(void* const* d_in, const int* in_sizes, int n_in,
                              void* d_out, int out_size)
{
    const float* x      = nullptr;
    const float* mask   = nullptr;
    const float* qkv_w  = nullptr;
    const float* qkv_b  = nullptr;
    const float* proj_w = nullptr;
    const float* proj_b = nullptr;
    const float* table  = nullptr;
    const int*   relidx = nullptr;

    for (int i = 0; i < n_in; i++) {
        switch (in_sizes[i]) {
            case 51380224: x      = (const float*)d_in[i]; break;
            case 153664:   mask   = (const float*)d_in[i]; break;
            case 786432:   qkv_w  = (const float*)d_in[i]; break;
            case 1536:     qkv_b  = (const float*)d_in[i]; break;
            case 262144:   proj_w = (const float*)d_in[i]; break;
            case 512:      proj_b = (const float*)d_in[i]; break;
            case 2704:     table  = (const float*)d_in[i]; break;
            case 2401:     relidx = (const int*)  d_in[i]; break;
            default: break;
        }
    }
    float* out = (float*)d_out;

    cudaFuncSetAttribute(gemm_tc<0>, cudaFuncAttributeMaxDynamicSharedMemorySize, SMEM_DYN);
    cudaFuncSetAttribute(gemm_tc<1>, cudaFuncAttributeMaxDynamicSharedMemorySize, SMEM_DYN);

    convert_split<0><<<(MROWS * CDIM / 4) / 256, 256>>>(x);
    convert_split<1><<<(QKVCOLS * CDIM / 4) / 256, 256>>>(qkv_w);
    convert_split<2><<<(CDIM * CDIM / 4) / 256, 256>>>(proj_w);

    {
        dim3 grid(QKVCOLS / 256, MROWS / 128);   // (6, 784)
        gemm_tc<0><<<grid, 512, SMEM_DYN>>>(qkv_b, nullptr);
    }
    {
        dim3 grid(NHEAD, B_TOT);
        attn_kernel<<<grid, 256>>>(mask, table, relidx);
    }
    {
        dim3 grid(CDIM / 256, MROWS / 128);      // (2, 784)
        gemm_tc<1><<<grid, 512, SMEM_DYN>>>(proj_b, out);
    }
}